// round 5
// baseline (speedup 1.0000x reference)
#include <cuda_runtime.h>
#include <cstdint>

// ---------------------------------------------------------------------------
// MSC_Cell: B=128, S=4096, STATE_DIM=5, HIDDEN=32, D_IN=9
// Kernel 1: per-batch-row inclusive prefix sum of delta_x[...,2] (+ init temp)
// Kernel 2: per-token gated-tanh MLP + state mix, f32x2-packed FMAs,
//           weights in SMEM (broadcast LDS.128), MUFU-based tanh/exp.
// ---------------------------------------------------------------------------

#define BB 128
#define SS 4096

__device__ float g_temp[BB * SS];

// ---- f32x2 helpers (sm_103a packed math; ptxas never auto-fuses these) ----
__device__ __forceinline__ unsigned long long pk2(float x) {
    unsigned long long r;
    asm("mov.b64 %0, {%1, %1};" : "=l"(r) : "f"(x));
    return r;
}
__device__ __forceinline__ unsigned long long f2fma(unsigned long long a,
                                                    unsigned long long b,
                                                    unsigned long long c) {
    unsigned long long d;
    asm("fma.rn.f32x2 %0, %1, %2, %3;" : "=l"(d) : "l"(a), "l"(b), "l"(c));
    return d;
}
__device__ __forceinline__ void unpk(unsigned long long v, float& lo, float& hi) {
    asm("mov.b64 {%0, %1}, %2;" : "=f"(lo), "=f"(hi) : "l"(v));
}

// tanh via EX2+RCP (MUFU). Saturation-safe: e=inf -> 2/(inf+1)=0 -> t=1.
__device__ __forceinline__ float tanh_pf(float x) {
    float ax = fabsf(x);
    float e  = __expf(ax + ax);
    float t  = 1.0f - __fdividef(2.0f, e + 1.0f);
    return copysignf(t, x);
}

// ---------------------------------------------------------------------------
// Kernel 1: prefix scan. One block per batch row, 512 threads x 8 elements.
// temp[b,s] = cumsum_{0..s}(dx[b,:,2]) + dx[b,0,5]
// ---------------------------------------------------------------------------
__global__ void scan_kernel(const float* __restrict__ dx) {
    int b = blockIdx.x;
    const float* base = dx + (size_t)b * SS * 6;
    int t = threadIdx.x;  // 0..511

    float v[8];
    float run = 0.0f;
#pragma unroll
    for (int j = 0; j < 8; j++) {
        run += base[(t * 8 + j) * 6 + 2];
        v[j] = run;
    }

    // inclusive scan of per-thread totals across 512 threads
    float incl = run;
    int lane = t & 31, wid = t >> 5;
#pragma unroll
    for (int o = 1; o < 32; o <<= 1) {
        float n = __shfl_up_sync(0xffffffffu, incl, o);
        if (lane >= o) incl += n;
    }
    __shared__ float wsum[16];
    if (lane == 31) wsum[wid] = incl;
    __syncthreads();
    float woff = 0.0f;
    for (int k = 0; k < wid; k++) woff += wsum[k];

    float excl = woff + incl - run;  // exclusive prefix for this thread
    float init = base[5];

    float* o = g_temp + (size_t)b * SS + t * 8;
#pragma unroll
    for (int j = 0; j < 8; j++) o[j] = excl + v[j] + init;
}

// ---------------------------------------------------------------------------
// SMEM layout (floats)
// ---------------------------------------------------------------------------
enum {
    A0_OFF = 0,      // Wa0: 9x32
    B0_OFF = 288,    // Wb0: 9x32
    A1_OFF = 576,    // Wa1: 32x32
    B1_OFF = 1600,   // Wb1: 32x32
    HD_OFF = 2624,   // head matrix 32x8: [alpha,beta,gamma,c0..c4]
    BA0_OFF = 2880,
    BB0_OFF = 2912,
    BA1_OFF = 2944,
    BB1_OFF = 2976,
    HB_OFF  = 3008,  // 8 head biases
    WO_OFF  = 3016,  // W_out: 5
    SW_TOTAL = 3040
};

// One gated MLP layer: lout[32] = tanh(lin@Wa + ba) * tanh(lin@Wb + bb)
template <int NIN>
__device__ __forceinline__ void mlp_layer(const float* __restrict__ lin,
                                          const float* sA, const float* sB,
                                          const float* sBa, const float* sBb,
                                          float* __restrict__ lout) {
    unsigned long long accA[16], accB[16];
#pragma unroll
    for (int p = 0; p < 16; p++) {
        accA[p] = *(const unsigned long long*)(sBa + 2 * p);
        accB[p] = *(const unsigned long long*)(sBb + 2 * p);
    }
#pragma unroll
    for (int i = 0; i < NIN; i++) {
        unsigned long long xb = pk2(lin[i]);
        const float* wa = sA + i * 32;
        const float* wb = sB + i * 32;
#pragma unroll
        for (int q = 0; q < 8; q++) {
            ulonglong2 wA = *(const ulonglong2*)(wa + 4 * q);
            ulonglong2 wB = *(const ulonglong2*)(wb + 4 * q);
            accA[2 * q]     = f2fma(xb, wA.x, accA[2 * q]);
            accA[2 * q + 1] = f2fma(xb, wA.y, accA[2 * q + 1]);
            accB[2 * q]     = f2fma(xb, wB.x, accB[2 * q]);
            accB[2 * q + 1] = f2fma(xb, wB.y, accB[2 * q + 1]);
        }
    }
#pragma unroll
    for (int p = 0; p < 16; p++) {
        float a0, a1, b0, b1;
        unpk(accA[p], a0, a1);
        unpk(accB[p], b0, b1);
        lout[2 * p]     = tanh_pf(a0) * tanh_pf(b0);
        lout[2 * p + 1] = tanh_pf(a1) * tanh_pf(b1);
    }
}

// ---------------------------------------------------------------------------
// Kernel 2: main per-token compute (one thread per token)
// ---------------------------------------------------------------------------
__global__ __launch_bounds__(256, 2) void msc_main(
    const float* __restrict__ h_prev, const float* __restrict__ dx,
    const float* __restrict__ Wa0, const float* __restrict__ ba0,
    const float* __restrict__ Wb0, const float* __restrict__ bb0,
    const float* __restrict__ Wa1, const float* __restrict__ ba1,
    const float* __restrict__ Wb1, const float* __restrict__ bb1,
    const float* __restrict__ W_alpha, const float* __restrict__ b_alpha,
    const float* __restrict__ W_beta,  const float* __restrict__ b_beta,
    const float* __restrict__ W_gamma, const float* __restrict__ b_gamma,
    const float* __restrict__ W_c,     const float* __restrict__ b_c,
    const float* __restrict__ W_out,
    float* __restrict__ out, int ntok) {
    __shared__ __align__(16) float sW[SW_TOTAL];
    int tid = threadIdx.x;

    // cooperative weight staging
    for (int i = tid; i < 288; i += 256) {
        sW[A0_OFF + i] = Wa0[i];
        sW[B0_OFF + i] = Wb0[i];
    }
    for (int i = tid; i < 1024; i += 256) {
        sW[A1_OFF + i] = Wa1[i];
        sW[B1_OFF + i] = Wb1[i];
    }
    {   // interleave head matrix: row i holds [alpha, beta, gamma, c0..c4]
        int i = tid >> 3, j = tid & 7;  // tid < 256 covers all 32x8
        float v;
        if (j == 0)      v = W_alpha[i];
        else if (j == 1) v = W_beta[i];
        else if (j == 2) v = W_gamma[i];
        else             v = W_c[i * 5 + (j - 3)];
        sW[HD_OFF + tid] = v;
    }
    if (tid < 32) {
        sW[BA0_OFF + tid] = ba0[tid];
        sW[BB0_OFF + tid] = bb0[tid];
        sW[BA1_OFF + tid] = ba1[tid];
        sW[BB1_OFF + tid] = bb1[tid];
    }
    if (tid < 8) {
        float v;
        if (tid == 0)      v = b_alpha[0];
        else if (tid == 1) v = b_beta[0];
        else if (tid == 2) v = b_gamma[0];
        else               v = b_c[tid - 3];
        sW[HB_OFF + tid] = v;
    }
    if (tid < 5) sW[WO_OFF + tid] = W_out[tid];
    __syncthreads();

    int token = blockIdx.x * 256 + tid;
    if (token >= ntok) return;

    const float* hp = h_prev + (size_t)token * 5;
    float h0 = hp[0], h1 = hp[1], h2 = hp[2], h3 = hp[3], h4 = hp[4];
    const float* dp = dx + (size_t)token * 6;
    float d0 = dp[0], d1 = dp[1], d2 = dp[2];
    float temp = g_temp[token];

    // direction
    float ss  = fmaf(d0, d0, fmaf(d1, d1, d2 * d2));
    float nrm = fmaxf(sqrtf(ss), 1e-7f);
    float inv = __fdividef(1.0f, nrm);

    float lin[9];
    lin[0] = h0; lin[1] = h1; lin[2] = h2; lin[3] = h3; lin[4] = h4;
    lin[5] = temp;
    lin[6] = d0 * inv; lin[7] = d1 * inv; lin[8] = d2 * inv;

    float l1[32], l2[32];
    mlp_layer<9>(lin, sW + A0_OFF, sW + B0_OFF, sW + BA0_OFF, sW + BB0_OFF, l1);
    mlp_layer<32>(l1, sW + A1_OFF, sW + B1_OFF, sW + BA1_OFF, sW + BB1_OFF, l2);

    // heads: 32x8 GEMV, 4 packed accumulators
    unsigned long long accH[4];
#pragma unroll
    for (int p = 0; p < 4; p++)
        accH[p] = *(const unsigned long long*)(sW + HB_OFF + 2 * p);
#pragma unroll
    for (int i = 0; i < 32; i++) {
        unsigned long long xb = pk2(l2[i]);
        const float* wh = sW + HD_OFF + i * 8;
        ulonglong2 w0 = *(const ulonglong2*)(wh);
        ulonglong2 w1 = *(const ulonglong2*)(wh + 4);
        accH[0] = f2fma(xb, w0.x, accH[0]);
        accH[1] = f2fma(xb, w0.y, accH[1]);
        accH[2] = f2fma(xb, w1.x, accH[2]);
        accH[3] = f2fma(xb, w1.y, accH[3]);
    }
    float aP, bP, gP, c0P, c1P, c2P, c3P, c4P;
    unpk(accH[0], aP, bP);
    unpk(accH[1], gP, c0P);
    unpk(accH[2], c1P, c2P);
    unpk(accH[3], c3P, c4P);

    float alpha = __expf(aP);
    float beta  = __expf(bP);
    float gamma = __expf(gP);
    float c0 = tanh_pf(c0P), c1 = tanh_pf(c1P), c2 = tanh_pf(c2P);
    float c3 = tanh_pf(c3P), c4 = tanh_pf(c4P);

    float zarg = fmaf(alpha, fabsf(d0), fmaf(beta, d1, gamma * fabsf(d2)));
    float z = 1.0f - __expf(-zarg);

    float n0 = fmaf(z, c0 - h0, h0);
    float n1 = fmaf(z, c1 - h1, h1);
    float n2 = fmaf(z, c2 - h2, h2);
    float n3 = fmaf(z, c3 - h3, h3);
    float n4 = fmaf(z, c4 - h4, h4);

    float sigma = n0 * sW[WO_OFF + 0];
    sigma = fmaf(n1, sW[WO_OFF + 1], sigma);
    sigma = fmaf(n2, sW[WO_OFF + 2], sigma);
    sigma = fmaf(n3, sW[WO_OFF + 3], sigma);
    sigma = fmaf(n4, sW[WO_OFF + 4], sigma);

    float* oh = out + (size_t)token * 5;
    oh[0] = n0; oh[1] = n1; oh[2] = n2; oh[3] = n3; oh[4] = n4;
    out[(size_t)ntok * 5 + token] = sigma;
}

// ---------------------------------------------------------------------------
extern "C" void kernel_launch(void* const* d_in, const int* in_sizes, int n_in,
                              void* d_out, int out_size) {
    const float* h_prev  = (const float*)d_in[0];
    const float* dx      = (const float*)d_in[1];
    const float* Wa0     = (const float*)d_in[2];
    const float* ba0     = (const float*)d_in[3];
    const float* Wb0     = (const float*)d_in[4];
    const float* bb0     = (const float*)d_in[5];
    const float* Wa1     = (const float*)d_in[6];
    const float* ba1     = (const float*)d_in[7];
    const float* Wb1     = (const float*)d_in[8];
    const float* bb1     = (const float*)d_in[9];
    const float* W_alpha = (const float*)d_in[10];
    const float* b_alpha = (const float*)d_in[11];
    const float* W_beta  = (const float*)d_in[12];
    const float* b_beta  = (const float*)d_in[13];
    const float* W_gamma = (const float*)d_in[14];
    const float* b_gamma = (const float*)d_in[15];
    const float* W_c     = (const float*)d_in[16];
    const float* b_c     = (const float*)d_in[17];
    const float* W_out   = (const float*)d_in[18];
    float* out = (float*)d_out;

    int ntok = in_sizes[0] / 5;        // B*S
    int batches = ntok / SS;           // B

    scan_kernel<<<batches, 512>>>(dx);

    int blocks = (ntok + 255) / 256;
    msc_main<<<blocks, 256>>>(h_prev, dx,
                              Wa0, ba0, Wb0, bb0, Wa1, ba1, Wb1, bb1,
                              W_alpha, b_alpha, W_beta, b_beta,
                              W_gamma, b_gamma, W_c, b_c, W_out,
                              out, ntok);
}

// round 8
// speedup vs baseline: 2.2270x; 2.2270x over previous
#include <cuda_runtime.h>
#include <cstdint>

// ---------------------------------------------------------------------------
// MSC_Cell: B=128, S=4096, STATE_DIM=5, HIDDEN=32, D_IN=9
// Kernel 1: per-batch-row prefix scan of delta_x[...,2] (+ init temp)
// Kernel 2: gated-tanh MLP, 2 tokens per thread (halves LDS per token),
//           f32x2 packed FMAs, tanh.approx.f32 (MUFU), 16-neuron half-split
//           to bound register pressure.
// ---------------------------------------------------------------------------

#define BB 128
#define SS 4096

__device__ float g_temp[BB * SS];

typedef unsigned long long ull;

// ---- f32x2 helpers ----
__device__ __forceinline__ ull pk2(float x) {
    ull r;
    asm("mov.b64 %0, {%1, %1};" : "=l"(r) : "f"(x));
    return r;
}
__device__ __forceinline__ ull f2fma(ull a, ull b, ull c) {
    ull d;
    asm("fma.rn.f32x2 %0, %1, %2, %3;" : "=l"(d) : "l"(a), "l"(b), "l"(c));
    return d;
}
__device__ __forceinline__ void unpk(ull v, float& lo, float& hi) {
    asm("mov.b64 {%0, %1}, %2;" : "=f"(lo), "=f"(hi) : "l"(v));
}
__device__ __forceinline__ float tanh_ap(float x) {
    float y;
    asm("tanh.approx.f32 %0, %1;" : "=f"(y) : "f"(x));
    return y;
}

// ---------------------------------------------------------------------------
// Kernel 1: prefix scan. One block per batch row, 512 threads x 8 elements.
// ---------------------------------------------------------------------------
__global__ void scan_kernel(const float* __restrict__ dx) {
    int b = blockIdx.x;
    const float* base = dx + (size_t)b * SS * 6;
    int t = threadIdx.x;  // 0..511

    float v[8];
    float run = 0.0f;
#pragma unroll
    for (int j = 0; j < 8; j++) {
        run += base[(t * 8 + j) * 6 + 2];
        v[j] = run;
    }

    float incl = run;
    int lane = t & 31, wid = t >> 5;
#pragma unroll
    for (int o = 1; o < 32; o <<= 1) {
        float n = __shfl_up_sync(0xffffffffu, incl, o);
        if (lane >= o) incl += n;
    }
    __shared__ float wsum[16];
    if (lane == 31) wsum[wid] = incl;
    __syncthreads();
    float woff = 0.0f;
    for (int k = 0; k < wid; k++) woff += wsum[k];

    float excl = woff + incl - run;
    float init = base[5];

    float* o = g_temp + (size_t)b * SS + t * 8;
#pragma unroll
    for (int j = 0; j < 8; j++) o[j] = excl + v[j] + init;
}

// ---------------------------------------------------------------------------
// SMEM layout (floats)
// ---------------------------------------------------------------------------
enum {
    A0_OFF = 0,      // Wa0: 9x32
    B0_OFF = 288,    // Wb0: 9x32
    A1_OFF = 576,    // Wa1: 32x32
    B1_OFF = 1600,   // Wb1: 32x32
    HD_OFF = 2624,   // head matrix 32x8: [alpha,beta,gamma,c0..c4]
    BA0_OFF = 2880,
    BB0_OFF = 2912,
    BA1_OFF = 2944,
    BB1_OFF = 2976,
    HB_OFF  = 3008,  // 8 head biases
    WO_OFF  = 3016,  // W_out: 5
    SW_TOTAL = 3040
};

// ---------------------------------------------------------------------------
// One gated layer for TWO tokens, processed in two 16-neuron halves.
// Each weight LDS feeds FMAs for both tokens.
// ---------------------------------------------------------------------------
template <int NIN>
__device__ __forceinline__ void mlp2(const float* __restrict__ x0v,
                                     const float* __restrict__ x1v,
                                     const float* sA, const float* sB,
                                     const float* sBa, const float* sBb,
                                     float* __restrict__ o0,
                                     float* __restrict__ o1) {
#pragma unroll
    for (int h = 0; h < 2; h++) {
        ull aA0[8], aA1[8], aB0[8], aB1[8];
#pragma unroll
        for (int p = 0; p < 8; p++) {
            ull vA = *(const ull*)(sBa + h * 16 + 2 * p);
            ull vB = *(const ull*)(sBb + h * 16 + 2 * p);
            aA0[p] = vA; aA1[p] = vA;
            aB0[p] = vB; aB1[p] = vB;
        }
#pragma unroll
        for (int i = 0; i < NIN; i++) {
            ull x0 = pk2(x0v[i]);
            ull x1 = pk2(x1v[i]);
            const float* wa = sA + i * 32 + h * 16;
            const float* wb = sB + i * 32 + h * 16;
            ulonglong2 wa01 = *(const ulonglong2*)(wa);
            ulonglong2 wa23 = *(const ulonglong2*)(wa + 4);
            ulonglong2 wa45 = *(const ulonglong2*)(wa + 8);
            ulonglong2 wa67 = *(const ulonglong2*)(wa + 12);
            ulonglong2 wb01 = *(const ulonglong2*)(wb);
            ulonglong2 wb23 = *(const ulonglong2*)(wb + 4);
            ulonglong2 wb45 = *(const ulonglong2*)(wb + 8);
            ulonglong2 wb67 = *(const ulonglong2*)(wb + 12);

            aA0[0] = f2fma(x0, wa01.x, aA0[0]);  aA1[0] = f2fma(x1, wa01.x, aA1[0]);
            aA0[1] = f2fma(x0, wa01.y, aA0[1]);  aA1[1] = f2fma(x1, wa01.y, aA1[1]);
            aA0[2] = f2fma(x0, wa23.x, aA0[2]);  aA1[2] = f2fma(x1, wa23.x, aA1[2]);
            aA0[3] = f2fma(x0, wa23.y, aA0[3]);  aA1[3] = f2fma(x1, wa23.y, aA1[3]);
            aA0[4] = f2fma(x0, wa45.x, aA0[4]);  aA1[4] = f2fma(x1, wa45.x, aA1[4]);
            aA0[5] = f2fma(x0, wa45.y, aA0[5]);  aA1[5] = f2fma(x1, wa45.y, aA1[5]);
            aA0[6] = f2fma(x0, wa67.x, aA0[6]);  aA1[6] = f2fma(x1, wa67.x, aA1[6]);
            aA0[7] = f2fma(x0, wa67.y, aA0[7]);  aA1[7] = f2fma(x1, wa67.y, aA1[7]);

            aB0[0] = f2fma(x0, wb01.x, aB0[0]);  aB1[0] = f2fma(x1, wb01.x, aB1[0]);
            aB0[1] = f2fma(x0, wb01.y, aB0[1]);  aB1[1] = f2fma(x1, wb01.y, aB1[1]);
            aB0[2] = f2fma(x0, wb23.x, aB0[2]);  aB1[2] = f2fma(x1, wb23.x, aB1[2]);
            aB0[3] = f2fma(x0, wb23.y, aB0[3]);  aB1[3] = f2fma(x1, wb23.y, aB1[3]);
            aB0[4] = f2fma(x0, wb45.x, aB0[4]);  aB1[4] = f2fma(x1, wb45.x, aB1[4]);
            aB0[5] = f2fma(x0, wb45.y, aB0[5]);  aB1[5] = f2fma(x1, wb45.y, aB1[5]);
            aB0[6] = f2fma(x0, wb67.x, aB0[6]);  aB1[6] = f2fma(x1, wb67.x, aB1[6]);
            aB0[7] = f2fma(x0, wb67.y, aB0[7]);  aB1[7] = f2fma(x1, wb67.y, aB1[7]);
        }
#pragma unroll
        for (int p = 0; p < 8; p++) {
            float a0, a1, b0, b1;
            unpk(aA0[p], a0, a1);
            unpk(aB0[p], b0, b1);
            o0[h * 16 + 2 * p]     = tanh_ap(a0) * tanh_ap(b0);
            o0[h * 16 + 2 * p + 1] = tanh_ap(a1) * tanh_ap(b1);
            unpk(aA1[p], a0, a1);
            unpk(aB1[p], b0, b1);
            o1[h * 16 + 2 * p]     = tanh_ap(a0) * tanh_ap(b0);
            o1[h * 16 + 2 * p + 1] = tanh_ap(a1) * tanh_ap(b1);
        }
    }
}

// Per-token epilogue after the head GEMV.
__device__ __forceinline__ void finish_token(
    float aP, float bP, float gP,
    float c0P, float c1P, float c2P, float c3P, float c4P,
    float h0, float h1, float h2, float h3, float h4,
    float d0, float d1, float d2,
    const float* sWO, float* __restrict__ out, int token, int ntok) {
    float alpha = __expf(aP);
    float beta  = __expf(bP);
    float gamma = __expf(gP);
    float c0 = tanh_ap(c0P), c1 = tanh_ap(c1P), c2 = tanh_ap(c2P);
    float c3 = tanh_ap(c3P), c4 = tanh_ap(c4P);

    float zarg = fmaf(alpha, fabsf(d0), fmaf(beta, d1, gamma * fabsf(d2)));
    float z = 1.0f - __expf(-zarg);

    float n0 = fmaf(z, c0 - h0, h0);
    float n1 = fmaf(z, c1 - h1, h1);
    float n2 = fmaf(z, c2 - h2, h2);
    float n3 = fmaf(z, c3 - h3, h3);
    float n4 = fmaf(z, c4 - h4, h4);

    float sigma = n0 * sWO[0];
    sigma = fmaf(n1, sWO[1], sigma);
    sigma = fmaf(n2, sWO[2], sigma);
    sigma = fmaf(n3, sWO[3], sigma);
    sigma = fmaf(n4, sWO[4], sigma);

    float* oh = out + (size_t)token * 5;
    oh[0] = n0; oh[1] = n1; oh[2] = n2; oh[3] = n3; oh[4] = n4;
    out[(size_t)ntok * 5 + token] = sigma;
}

// ---------------------------------------------------------------------------
// Kernel 2: 128 threads/block, 2 tokens per thread (t and t+128).
// ---------------------------------------------------------------------------
__global__ __launch_bounds__(128) void msc_main(
    const float* __restrict__ h_prev, const float* __restrict__ dx,
    const float* __restrict__ Wa0, const float* __restrict__ ba0,
    const float* __restrict__ Wb0, const float* __restrict__ bb0,
    const float* __restrict__ Wa1, const float* __restrict__ ba1,
    const float* __restrict__ Wb1, const float* __restrict__ bb1,
    const float* __restrict__ W_alpha, const float* __restrict__ b_alpha,
    const float* __restrict__ W_beta,  const float* __restrict__ b_beta,
    const float* __restrict__ W_gamma, const float* __restrict__ b_gamma,
    const float* __restrict__ W_c,     const float* __restrict__ b_c,
    const float* __restrict__ W_out,
    float* __restrict__ out, int ntok) {
    __shared__ __align__(16) float sW[SW_TOTAL];
    int tid = threadIdx.x;

    // cooperative weight staging (128 threads)
    for (int i = tid; i < 288; i += 128) {
        sW[A0_OFF + i] = Wa0[i];
        sW[B0_OFF + i] = Wb0[i];
    }
    for (int i = tid; i < 1024; i += 128) {
        sW[A1_OFF + i] = Wa1[i];
        sW[B1_OFF + i] = Wb1[i];
    }
    for (int idx = tid; idx < 256; idx += 128) {
        int i = idx >> 3, j = idx & 7;  // head matrix row i: [alpha,beta,gamma,c0..c4]
        float v;
        if (j == 0)      v = W_alpha[i];
        else if (j == 1) v = W_beta[i];
        else if (j == 2) v = W_gamma[i];
        else             v = W_c[i * 5 + (j - 3)];
        sW[HD_OFF + idx] = v;
    }
    if (tid < 32) {
        sW[BA0_OFF + tid] = ba0[tid];
        sW[BB0_OFF + tid] = bb0[tid];
        sW[BA1_OFF + tid] = ba1[tid];
        sW[BB1_OFF + tid] = bb1[tid];
    }
    if (tid < 8) {
        float v;
        if (tid == 0)      v = b_alpha[0];
        else if (tid == 1) v = b_beta[0];
        else if (tid == 2) v = b_gamma[0];
        else               v = b_c[tid - 3];
        sW[HB_OFF + tid] = v;
    }
    if (tid < 5) sW[WO_OFF + tid] = W_out[tid];
    __syncthreads();

    int t0 = blockIdx.x * 256 + tid;
    int t1 = t0 + 128;
    if (t1 >= ntok) {  // exact grids never take this, kept for safety
        if (t0 >= ntok) return;
        t1 = t0;
    }

    // -------- per-token input prep (front-batched global loads) --------
    const float* hp0 = h_prev + (size_t)t0 * 5;
    const float* hp1 = h_prev + (size_t)t1 * 5;
    const float* dp0 = dx + (size_t)t0 * 6;
    const float* dp1 = dx + (size_t)t1 * 6;
    float h00 = hp0[0], h01 = hp0[1], h02 = hp0[2], h03 = hp0[3], h04 = hp0[4];
    float h10 = hp1[0], h11 = hp1[1], h12 = hp1[2], h13 = hp1[3], h14 = hp1[4];
    float d00 = dp0[0], d01 = dp0[1], d02 = dp0[2];
    float d10 = dp1[0], d11 = dp1[1], d12 = dp1[2];
    float tmp0 = g_temp[t0];
    float tmp1 = g_temp[t1];

    float lin0[9], lin1[9];
    {
        float ss  = fmaf(d00, d00, fmaf(d01, d01, d02 * d02));
        float inv = __fdividef(1.0f, fmaxf(sqrtf(ss), 1e-7f));
        lin0[0] = h00; lin0[1] = h01; lin0[2] = h02; lin0[3] = h03; lin0[4] = h04;
        lin0[5] = tmp0;
        lin0[6] = d00 * inv; lin0[7] = d01 * inv; lin0[8] = d02 * inv;
    }
    {
        float ss  = fmaf(d10, d10, fmaf(d11, d11, d12 * d12));
        float inv = __fdividef(1.0f, fmaxf(sqrtf(ss), 1e-7f));
        lin1[0] = h10; lin1[1] = h11; lin1[2] = h12; lin1[3] = h13; lin1[4] = h14;
        lin1[5] = tmp1;
        lin1[6] = d10 * inv; lin1[7] = d11 * inv; lin1[8] = d12 * inv;
    }

    float l1a[32], l1b[32];
    mlp2<9>(lin0, lin1, sW + A0_OFF, sW + B0_OFF, sW + BA0_OFF, sW + BB0_OFF,
            l1a, l1b);
    float l2a[32], l2b[32];
    mlp2<32>(l1a, l1b, sW + A1_OFF, sW + B1_OFF, sW + BA1_OFF, sW + BB1_OFF,
             l2a, l2b);

    // -------- heads: 32x8 GEMV for both tokens --------
    ull aH0[4], aH1[4];
#pragma unroll
    for (int p = 0; p < 4; p++) {
        ull v = *(const ull*)(sW + HB_OFF + 2 * p);
        aH0[p] = v; aH1[p] = v;
    }
#pragma unroll
    for (int i = 0; i < 32; i++) {
        ull x0 = pk2(l2a[i]);
        ull x1 = pk2(l2b[i]);
        const float* wh = sW + HD_OFF + i * 8;
        ulonglong2 w01 = *(const ulonglong2*)(wh);
        ulonglong2 w23 = *(const ulonglong2*)(wh + 4);
        aH0[0] = f2fma(x0, w01.x, aH0[0]);  aH1[0] = f2fma(x1, w01.x, aH1[0]);
        aH0[1] = f2fma(x0, w01.y, aH0[1]);  aH1[1] = f2fma(x1, w01.y, aH1[1]);
        aH0[2] = f2fma(x0, w23.x, aH0[2]);  aH1[2] = f2fma(x1, w23.x, aH1[2]);
        aH0[3] = f2fma(x0, w23.y, aH0[3]);  aH1[3] = f2fma(x1, w23.y, aH1[3]);
    }

    {
        float aP, bP, gP, c0P, c1P, c2P, c3P, c4P;
        unpk(aH0[0], aP, bP);
        unpk(aH0[1], gP, c0P);
        unpk(aH0[2], c1P, c2P);
        unpk(aH0[3], c3P, c4P);
        finish_token(aP, bP, gP, c0P, c1P, c2P, c3P, c4P,
                     h00, h01, h02, h03, h04, d00, d01, d02,
                     sW + WO_OFF, out, t0, ntok);
    }
    {
        float aP, bP, gP, c0P, c1P, c2P, c3P, c4P;
        unpk(aH1[0], aP, bP);
        unpk(aH1[1], gP, c0P);
        unpk(aH1[2], c1P, c2P);
        unpk(aH1[3], c3P, c4P);
        finish_token(aP, bP, gP, c0P, c1P, c2P, c3P, c4P,
                     h10, h11, h12, h13, h14, d10, d11, d12,
                     sW + WO_OFF, out, t1, ntok);
    }
}

// ---------------------------------------------------------------------------
extern "C" void kernel_launch(void* const* d_in, const int* in_sizes, int n_in,
                              void* d_out, int out_size) {
    const float* h_prev  = (const float*)d_in[0];
    const float* dx      = (const float*)d_in[1];
    const float* Wa0     = (const float*)d_in[2];
    const float* ba0     = (const float*)d_in[3];
    const float* Wb0     = (const float*)d_in[4];
    const float* bb0     = (const float*)d_in[5];
    const float* Wa1     = (const float*)d_in[6];
    const float* ba1     = (const float*)d_in[7];
    const float* Wb1     = (const float*)d_in[8];
    const float* bb1     = (const float*)d_in[9];
    const float* W_alpha = (const float*)d_in[10];
    const float* b_alpha = (const float*)d_in[11];
    const float* W_beta  = (const float*)d_in[12];
    const float* b_beta  = (const float*)d_in[13];
    const float* W_gamma = (const float*)d_in[14];
    const float* b_gamma = (const float*)d_in[15];
    const float* W_c     = (const float*)d_in[16];
    const float* b_c     = (const float*)d_in[17];
    const float* W_out   = (const float*)d_in[18];
    float* out = (float*)d_out;

    int ntok = in_sizes[0] / 5;   // B*S
    int batches = ntok / SS;      // B

    scan_kernel<<<batches, 512>>>(dx);

    int blocks = (ntok + 255) / 256;  // 256 tokens per block (128 thr x 2)
    msc_main<<<blocks, 128>>>(h_prev, dx,
                              Wa0, ba0, Wb0, bb0, Wa1, ba1, Wb1, bb1,
                              W_alpha, b_alpha, W_beta, b_beta,
                              W_gamma, b_gamma, W_c, b_c, W_out,
                              out, ntok);
}